// round 4
// baseline (speedup 1.0000x reference)
#include <cuda_runtime.h>
#include <cstdint>

// SparseBMM: C[b] = A[b] @ B[b]
//  A: [8, 4096, 4096] f32, ~80% of 128x128 tiles exactly zero
//  B: [8, 4096, 128] f32;  C: [8, 4096, 128] f32
//
// Software-pipelined A stream: the register tile for step kt+1 is prefetched
// BEFORE the compute of step kt, so A LDGs drain under the FFMA2 phase
// instead of serializing with it. Zero steps skip the A->smem store, the
// B load, and all math.

#define BATCHES 8
#define MDIM    4096
#define KDIM    4096
#define NDIM    128
#define MT      64
#define KT      64
#define KSTEPS  (KDIM / KT)
#define NTHREADS 128

#define AS_STRIDE (KT + 1)
#define SMEM_FLOATS (MT * AS_STRIDE + KT * NDIM)
#define SMEM_BYTES  (SMEM_FLOATS * 4)

__global__ __launch_bounds__(NTHREADS, 4)
void sparse_bmm_kernel(const float* __restrict__ A,
                       const float* __restrict__ B,
                       float* __restrict__ C) {
    extern __shared__ float sm[];
    float* As = sm;                     // [MT][AS_STRIDE]
    float* Bs = sm + MT * AS_STRIDE;    // [KT][NDIM]

    const int bidx  = blockIdx.x;       // 0..511
    const int batch = bidx >> 6;
    const int mt    = bidx & 63;

    const float* Ab = A + (size_t)batch * MDIM * KDIM + (size_t)mt * MT * KDIM;
    const float* Bb = B + (size_t)batch * KDIM * NDIM;
    float*       Cb = C + (size_t)batch * MDIM * NDIM + (size_t)mt * MT * NDIM;

    const int tid = threadIdx.x;
    const int tx  = tid & 15;   // 8 output cols each
    const int ty  = tid >> 4;   // 8 output rows each

    // Per-thread A-load geometry: slot t covers row (ty + 8t), float4-col tx.
    const float* a_base = Ab + (size_t)ty * KDIM + tx * 4;

    unsigned long long acc[8][4];
#pragma unroll
    for (int i = 0; i < 8; i++)
#pragma unroll
        for (int p = 0; p < 4; p++) acc[i][p] = 0ull;

    // prologue: load tile kt=0 into registers
    uint4 av[8];
#pragma unroll
    for (int t = 0; t < 8; t++)
        av[t] = *(const uint4*)(a_base + (size_t)(t * 8) * KDIM);

    for (int kt = 0; kt < KSTEPS; kt++) {
        // nonzero detection (integer OR; -0.0 false positive is harmless)
        unsigned nzb = 0;
#pragma unroll
        for (int t = 0; t < 8; t++)
            nzb |= av[t].x | av[t].y | av[t].z | av[t].w;

        // Barrier also orders: all compute of step kt-1 done before we
        // overwrite As / Bs below.
        const int flag = __syncthreads_or(nzb != 0u);

        if (flag) {
            // store A tile to smem (scalar stores: stride 65 breaks 16B
            // alignment on odd rows; only done on ~20% of steps)
#pragma unroll
            for (int t = 0; t < 8; t++) {
                float* p = As + (ty + t * 8) * AS_STRIDE + tx * 4;
                p[0] = __uint_as_float(av[t].x);
                p[1] = __uint_as_float(av[t].y);
                p[2] = __uint_as_float(av[t].z);
                p[3] = __uint_as_float(av[t].w);
            }
        }

        // prefetch A tile kt+1 (drains during compute / next steps)
        {
            const int ktn = (kt + 1 < KSTEPS) ? (kt + 1) : kt;  // uniform clamp
            const float* ap = a_base + ktn * KT;
#pragma unroll
            for (int t = 0; t < 8; t++)
                av[t] = *(const uint4*)(ap + (size_t)(t * 8) * KDIM);
        }

        if (flag) {
            // load 64x128 B tile (L2-resident)
            const float4* Bg = (const float4*)(Bb + (size_t)kt * KT * NDIM);
            float4* Bs4 = (float4*)Bs;
#pragma unroll
            for (int t = 0; t < 16; t++)
                Bs4[tid + t * NTHREADS] = Bg[tid + t * NTHREADS];
            __syncthreads();

            // compute: packed f32x2 FMAs
            const float* arow = As + (ty * 8) * AS_STRIDE;
#pragma unroll 8
            for (int kk = 0; kk < KT; kk++) {
                unsigned long long bb[4];
                const unsigned long long* bp =
                    (const unsigned long long*)(Bs + kk * NDIM + tx * 8);
#pragma unroll
                for (int p = 0; p < 4; p++) bb[p] = bp[p];

                unsigned long long aa[8];
#pragma unroll
                for (int i = 0; i < 8; i++) {
                    float a = arow[i * AS_STRIDE + kk];
                    asm("mov.b64 %0, {%1, %1};" : "=l"(aa[i]) : "f"(a));
                }
#pragma unroll
                for (int i = 0; i < 8; i++)
#pragma unroll
                    for (int p = 0; p < 4; p++)
                        asm("fma.rn.f32x2 %0, %1, %2, %0;"
                            : "+l"(acc[i][p])
                            : "l"(aa[i]), "l"(bb[p]));
            }
        }
    }

    // epilogue
#pragma unroll
    for (int i = 0; i < 8; i++) {
        float* crow = Cb + (size_t)(ty * 8 + i) * NDIM + tx * 8;
#pragma unroll
        for (int p = 0; p < 4; p++)
            *(unsigned long long*)(crow + p * 2) = acc[i][p];
    }
}

extern "C" void kernel_launch(void* const* d_in, const int* in_sizes, int n_in,
                              void* d_out, int out_size) {
    const float* a = (const float*)d_in[0];
    const float* b = (const float*)d_in[1];
    float* c = (float*)d_out;

    cudaFuncSetAttribute(sparse_bmm_kernel,
                         cudaFuncAttributeMaxDynamicSharedMemorySize,
                         SMEM_BYTES);

    dim3 grid(BATCHES * (MDIM / MT));   // 512 CTAs
    sparse_bmm_kernel<<<grid, NTHREADS, SMEM_BYTES>>>(a, b, c);
}

// round 5
// speedup vs baseline: 1.2134x; 1.2134x over previous
#include <cuda_runtime.h>
#include <cstdint>

// SparseBMM: C[b] = A[b] @ B[b]
//  A: [8, 4096, 4096] f32, ~80% of 128x128 tiles exactly zero
//  B: [8, 4096, 128] f32;  C: [8, 4096, 128] f32
//
// Round 5: cp.async double-buffered A pipeline (no registers held across
// compute -> no spills). MT=128 rows per CTA, 256 threads, 2 CTAs/SM,
// whole 256-CTA grid resident in one wave. Zero steps skip B load + math.
// Compute uses fma.rn.f32x2 with A read as float4 vectorized over kk.

#define BATCHES 8
#define MDIM    4096
#define KDIM    4096
#define NDIM    128
#define MT      128
#define KT      64
#define KSTEPS  (KDIM / KT)
#define NTHREADS 256

#define A_TILE_FLOATS (MT * KT)     // 8192 floats = 32KB
#define B_TILE_FLOATS (KT * NDIM)   // 8192 floats = 32KB
#define SMEM_FLOATS (2 * A_TILE_FLOATS + B_TILE_FLOATS)
#define SMEM_BYTES  (SMEM_FLOATS * 4)   // 96KB

__device__ __forceinline__ void cp_async16(uint32_t dst_smem, const float* src) {
    asm volatile("cp.async.cg.shared.global [%0], [%1], 16;"
                 :: "r"(dst_smem), "l"(src));
}
__device__ __forceinline__ void cp_commit() {
    asm volatile("cp.async.commit_group;");
}
__device__ __forceinline__ void cp_wait_1() {
    asm volatile("cp.async.wait_group 1;");
}

__global__ __launch_bounds__(NTHREADS, 2)
void sparse_bmm_kernel(const float* __restrict__ A,
                       const float* __restrict__ B,
                       float* __restrict__ C) {
    extern __shared__ float sm[];
    float* Ab0 = sm;                        // A buffer 0 [128][64]
    float* Ab1 = sm + A_TILE_FLOATS;        // A buffer 1
    float* Bs  = sm + 2 * A_TILE_FLOATS;    // B tile [64][128]

    const int bidx  = blockIdx.x;           // 0..255
    const int batch = bidx >> 5;            // 32 M-tiles per batch
    const int mt    = bidx & 31;

    const float* Ag = A + (size_t)batch * MDIM * KDIM + (size_t)mt * MT * KDIM;
    const float* Bg = B + (size_t)batch * KDIM * NDIM;
    float*       Cg = C + (size_t)batch * MDIM * NDIM + (size_t)mt * MT * NDIM;

    const int tid = threadIdx.x;
    const int tx  = tid & 15;    // 8 output cols each
    const int ty  = tid >> 4;    // 8 output rows each (16 row-groups)

    // cp.async chunk geometry: chunk c = tid + 256*t (t<8), row = c>>4,
    // 16B-col = c&15. Each thread copies and later nz-checks the SAME chunks.
    const int c_row  = tid >> 4;        // base row for t=0 (rows step by 16)
    const int c_col4 = tid & 15;        // float4 column within row

    uint32_t sa0 = (uint32_t)__cvta_generic_to_shared(Ab0);
    uint32_t sa1 = (uint32_t)__cvta_generic_to_shared(Ab1);

    unsigned long long acc[8][4];
#pragma unroll
    for (int i = 0; i < 8; i++)
#pragma unroll
        for (int p = 0; p < 4; p++) acc[i][p] = 0ull;

    // ---- prologue: start async load of tile 0 ----
#pragma unroll
    for (int t = 0; t < 8; t++) {
        int row = c_row + t * 16;
        cp_async16(sa0 + (uint32_t)(row * KT + c_col4 * 4) * 4,
                   Ag + (size_t)row * KDIM + c_col4 * 4);
    }
    cp_commit();

    for (int kt = 0; kt < KSTEPS; kt++) {
        const int cur = kt & 1;
        float* Acur = cur ? Ab1 : Ab0;

        // ---- issue async load of tile kt+1 into the other buffer ----
        if (kt + 1 < KSTEPS) {
            uint32_t sdst = cur ? sa0 : sa1;
            const float* asrc = Ag + (size_t)(kt + 1) * KT;
#pragma unroll
            for (int t = 0; t < 8; t++) {
                int row = c_row + t * 16;
                cp_async16(sdst + (uint32_t)(row * KT + c_col4 * 4) * 4,
                           asrc + (size_t)row * KDIM + c_col4 * 4);
            }
        }
        cp_commit();   // always commit (possibly empty group) so wait_1 is exact

        // ---- wait for tile kt; check own chunks for nonzero ----
        cp_wait_1();
        unsigned nz = 0;
#pragma unroll
        for (int t = 0; t < 8; t++) {
            const uint4 v = *(const uint4*)(Acur + (c_row + t * 16) * KT + c_col4 * 4);
            nz |= v.x | v.y | v.z | v.w;
        }
        // Barrier: publishes this thread's cp.async data to all threads AND
        // orders all nz reads of Acur before next iteration's cp.async issue.
        const int flag = __syncthreads_or(nz != 0u);

        if (flag) {
            // ---- stage B tile [64][128] (L2-resident; shared by 32 CTAs) ----
            const float4* Bsrc = (const float4*)(Bg + (size_t)kt * KT * NDIM);
            float4* Bdst = (float4*)Bs;
#pragma unroll
            for (int t = 0; t < 8; t++)
                Bdst[tid + t * NTHREADS] = Bsrc[tid + t * NTHREADS];
            __syncthreads();

            // ---- compute: A via float4 over kk, packed f32x2 FMAs ----
            const float* arow = Acur + (ty * 8) * KT;
#pragma unroll
            for (int kk0 = 0; kk0 < KT; kk0 += 4) {
#pragma unroll
                for (int h = 0; h < 2; h++) {
                    float4 a4[4];
#pragma unroll
                    for (int i = 0; i < 4; i++)
                        a4[i] = *(const float4*)(arow + (h * 4 + i) * KT + kk0);
#pragma unroll
                    for (int s = 0; s < 4; s++) {
                        unsigned long long bb[4];
                        const unsigned long long* bp =
                            (const unsigned long long*)(Bs + (kk0 + s) * NDIM + tx * 8);
#pragma unroll
                        for (int p = 0; p < 4; p++) bb[p] = bp[p];

#pragma unroll
                        for (int i = 0; i < 4; i++) {
                            float a = (s == 0) ? a4[i].x :
                                      (s == 1) ? a4[i].y :
                                      (s == 2) ? a4[i].z : a4[i].w;
                            unsigned long long aa;
                            asm("mov.b64 %0, {%1, %1};" : "=l"(aa) : "f"(a));
#pragma unroll
                            for (int p = 0; p < 4; p++)
                                asm("fma.rn.f32x2 %0, %1, %2, %0;"
                                    : "+l"(acc[h * 4 + i][p])
                                    : "l"(aa), "l"(bb[p]));
                        }
                    }
                }
            }
            // Protect Acur (read above) from next iteration's cp.async into
            // the same buffer (used again at step kt+2), and Bs from reuse.
            __syncthreads();
        }
    }

    // ---- epilogue ----
#pragma unroll
    for (int i = 0; i < 8; i++) {
        float* crow = Cg + (size_t)(ty * 8 + i) * NDIM + tx * 8;
        uint4 v0, v1;
        v0.x = (unsigned)acc[i][0]; v0.y = (unsigned)(acc[i][0] >> 32);
        v0.z = (unsigned)acc[i][1]; v0.w = (unsigned)(acc[i][1] >> 32);
        v1.x = (unsigned)acc[i][2]; v1.y = (unsigned)(acc[i][2] >> 32);
        v1.z = (unsigned)acc[i][3]; v1.w = (unsigned)(acc[i][3] >> 32);
        *(uint4*)(crow)     = v0;
        *(uint4*)(crow + 4) = v1;
    }
}

extern "C" void kernel_launch(void* const* d_in, const int* in_sizes, int n_in,
                              void* d_out, int out_size) {
    const float* a = (const float*)d_in[0];
    const float* b = (const float*)d_in[1];
    float* c = (float*)d_out;

    cudaFuncSetAttribute(sparse_bmm_kernel,
                         cudaFuncAttributeMaxDynamicSharedMemorySize,
                         SMEM_BYTES);

    dim3 grid(BATCHES * (MDIM / MT));   // 256 CTAs, one resident wave
    sparse_bmm_kernel<<<grid, NTHREADS, SMEM_BYTES>>>(a, b, c);
}